// round 9
// baseline (speedup 1.0000x reference)
#include <cuda_runtime.h>
#include <cuda_bf16.h>
#include <math.h>
#include <stdint.h>

// ---------------- problem constants ----------------
#define BB   16
#define SS   1024
#define DIN  768
#define EE   512
#define HH   8
#define LL   2
#define FF   2048
#define DH   64
#define MTOK (BB*SS)          // 16384 rows

// ---------------- scratch ----------------
__device__ float g_x  [MTOK*EE];
__device__ float g_a  [MTOK*EE];
__device__ float g_qkv[MTOK*3*EE];
__device__ float g_o  [MTOK*EE];
__device__ float g_f  [MTOK*FF];
__device__ float g_xp [MTOK*EE];
__device__ float g_h  [BB*EE];
__device__ float g_wr [7208960];        // permuted+tf32-rounded weight copies

// rounded-weight offsets
#define OFF_WP   0
#define OFF_WQKV 393216
#define OFF_WO   1966080
#define OFF_W1   2490368
#define OFF_W2   4587520
#define OFF_WI   6684672

// ---------------- helpers ----------------
__device__ __forceinline__ float gelu_exact(float x) {
    return 0.5f * x * (1.0f + erff(x * 0.7071067811865476f));
}
__device__ __forceinline__ void cpasync16(uint32_t dst, const void* src) {
    asm volatile("cp.async.cg.shared.global [%0], [%1], 16;" :: "r"(dst), "l"(src));
}
__device__ __forceinline__ void cp_commit() { asm volatile("cp.async.commit_group;"); }
__device__ __forceinline__ void cp_wait1() { asm volatile("cp.async.wait_group 1;"); }
__device__ __forceinline__ void cp_wait0() { asm volatile("cp.async.wait_group 0;"); }
__device__ __forceinline__ uint32_t smem_u32(const void* p) {
    uint32_t a;
    asm("{ .reg .u64 t; cvta.to.shared.u64 t, %1; cvt.u32.u64 %0, t; }" : "=r"(a) : "l"(p));
    return a;
}
__device__ __forceinline__ uint32_t f2tf(float f) {
    uint32_t u;
    asm("cvt.rna.tf32.f32 %0, %1;" : "=r"(u) : "f"(f));
    return u;
}
__device__ __forceinline__ float roundtf(float f) {
    return __uint_as_float(f2tf(f));
}
__device__ __forceinline__ void mma_tf32(float* c, const uint32_t* a, const uint32_t* b) {
    asm volatile(
        "mma.sync.aligned.m16n8k8.row.col.f32.tf32.tf32.f32 "
        "{%0,%1,%2,%3}, {%4,%5,%6,%7}, {%8,%9}, {%0,%1,%2,%3};"
        : "+f"(c[0]), "+f"(c[1]), "+f"(c[2]), "+f"(c[3])
        : "r"(a[0]), "r"(a[1]), "r"(a[2]), "r"(a[3]), "r"(b[0]), "r"(b[1]));
}
// permuted position within a 32-float block: p(k) = (k%4)*8 + (k%32)/4
__device__ __forceinline__ int permcol(int cc) {
    return (cc & ~31) + (cc & 3) * 8 + ((cc & 31) >> 2);
}

// =====================================================================
// Weight prep: dst[i] = roundtf(src[perm_inverse(i)]) — block-32 permute.
// dst position p (within block): c = p>>3, j = p&7  ->  src k = c + 4*j.
// =====================================================================
__global__ void permute_round_kernel(const float* __restrict__ src,
                                     float* __restrict__ dst, int n)
{
    int i = blockIdx.x * 256 + threadIdx.x;
    if (i >= n) return;
    int p = i & 31;
    int base = i - p;
    dst[i] = roundtf(src[base + (p >> 3) + ((p & 7) << 2)]);
}

// =====================================================================
// tf32 warp-MMA GEMM: C[M,N] = epi( A[M,K] * B^T + bias )
//   B always block-permuted tf32 (g_wr) -> vectorized fragment loads.
//   APERM: A block-permuted tf32 -> vectorized; else raw f32 (scalar+cvt).
//   RND: round outputs. OUTPERM: write C in block-permuted layout.
//   EPI: 0=bias, 1=bias+gelu, 2=C += acc + bias
//   SMEM rows padded to 36 floats (144B) -> conflict-free frag loads.
// =====================================================================
#define ROWB 144
#define ASTG (128*ROWB)
#define STGS (2*ASTG)
static const int GEMM_SMEM = 3 * STGS;   // 110592

template<int EPI, bool APERM, bool RND, bool OUTPERM>
__global__ void __launch_bounds__(256, 2)
gemm_mma(const float* __restrict__ A, const float* __restrict__ B,
         const float* __restrict__ bias, float* __restrict__ C,
         int M, int N, int K, int lda, int ldb, int ldc)
{
    extern __shared__ char smem[];
    const uint32_t sb = smem_u32(smem);

    const int tid = threadIdx.x;
    const int wid = tid >> 5;
    const int lane = tid & 31;
    const int g  = lane >> 2;
    const int tg = lane & 3;
    const int wm = wid & 3;
    const int wn = wid >> 2;
    const int bm = blockIdx.y * 128;
    const int bn = blockIdx.x * 128;

    const int NC = K >> 5;

    float acc[2][8][4];
    #pragma unroll
    for (int i = 0; i < 2; i++)
        #pragma unroll
        for (int j = 0; j < 8; j++)
            #pragma unroll
            for (int q = 0; q < 4; q++) acc[i][j][q] = 0.f;

    auto loadA = [&](int stage, int k0) {
        uint32_t base = sb + stage * STGS;
        const float* src0 = A + (long long)bm * lda + k0;
        #pragma unroll
        for (int i = 0; i < 4; i++) {
            int j = tid + i * 256;
            int row = j >> 3;
            int c4  = (j & 7) * 4;
            cpasync16(base + row * ROWB + c4 * 4,
                      src0 + (long long)row * lda + c4);
        }
    };
    auto loadB = [&](int stage, int k0) {
        uint32_t base = sb + stage * STGS + ASTG;
        const float* src0 = B + (long long)bn * ldb + k0;
        #pragma unroll
        for (int i = 0; i < 4; i++) {
            int j = tid + i * 256;
            int row = j >> 3;
            int c4  = (j & 7) * 4;
            cpasync16(base + row * ROWB + c4 * 4,
                      src0 + (long long)row * ldb + c4);
        }
    };

    auto compute = [&](int stage) {
        const char* Ab = smem + stage * STGS;
        const char* Bb = Ab + ASTG;
        // A fragments for the whole chunk: 4 rows x 8 values (k = tg + 4j)
        uint32_t af[4][8];
        #pragma unroll
        for (int rr = 0; rr < 4; rr++) {
            int row = wm * 32 + rr * 8 + g;
            if (APERM) {
                float4 v0 = *(const float4*)(Ab + row * ROWB + tg * 32);
                float4 v1 = *(const float4*)(Ab + row * ROWB + tg * 32 + 16);
                af[rr][0] = __float_as_uint(v0.x); af[rr][1] = __float_as_uint(v0.y);
                af[rr][2] = __float_as_uint(v0.z); af[rr][3] = __float_as_uint(v0.w);
                af[rr][4] = __float_as_uint(v1.x); af[rr][5] = __float_as_uint(v1.y);
                af[rr][6] = __float_as_uint(v1.z); af[rr][7] = __float_as_uint(v1.w);
            } else {
                #pragma unroll
                for (int jj = 0; jj < 8; jj++)
                    af[rr][jj] = f2tf(*(const float*)(Ab + row * ROWB + (tg + 4 * jj) * 4));
            }
        }
        #pragma unroll
        for (int na = 0; na < 8; na++) {
            int rn = wn * 64 + na * 8 + g;
            float4 b0 = *(const float4*)(Bb + rn * ROWB + tg * 32);
            float4 b1 = *(const float4*)(Bb + rn * ROWB + tg * 32 + 16);
            uint32_t bf[8];
            bf[0] = __float_as_uint(b0.x); bf[1] = __float_as_uint(b0.y);
            bf[2] = __float_as_uint(b0.z); bf[3] = __float_as_uint(b0.w);
            bf[4] = __float_as_uint(b1.x); bf[5] = __float_as_uint(b1.y);
            bf[6] = __float_as_uint(b1.z); bf[7] = __float_as_uint(b1.w);
            #pragma unroll
            for (int ma = 0; ma < 2; ma++)
                #pragma unroll
                for (int kk = 0; kk < 4; kk++) {
                    uint32_t a[4] = {af[ma * 2][2 * kk], af[ma * 2 + 1][2 * kk],
                                     af[ma * 2][2 * kk + 1], af[ma * 2 + 1][2 * kk + 1]};
                    mma_tf32(acc[ma][na], a, bf + 2 * kk);
                }
        }
    };

    // ---------- 3-stage pipelined mainloop ----------
    loadA(0, 0); loadB(0, 0); cp_commit();
    loadA(1, 32); loadB(1, 32); cp_commit();
    for (int c = 0; c < NC; c++) {
        if (c + 1 < NC) cp_wait1(); else cp_wait0();
        __syncthreads();
        if (c + 2 < NC) {
            int s = (c + 2) % 3;
            loadA(s, (c + 2) << 5); loadB(s, (c + 2) << 5); cp_commit();
        }
        compute(c % 3);
    }

    // ---------- epilogue ----------
    #pragma unroll
    for (int ma = 0; ma < 2; ma++) {
        int row0 = bm + wm * 32 + ma * 16 + g;
        #pragma unroll
        for (int na = 0; na < 8; na++) {
            int col = bn + wn * 64 + na * 8 + tg * 2;
            #pragma unroll
            for (int half = 0; half < 2; half++) {
                int row = row0 + half * 8;
                float2 v;
                v.x = acc[ma][na][half * 2 + 0];
                v.y = acc[ma][na][half * 2 + 1];
                if (bias) { v.x += bias[col]; v.y += bias[col + 1]; }
                if (EPI == 1) { v.x = gelu_exact(v.x); v.y = gelu_exact(v.y); }
                if (RND) { v.x = roundtf(v.x); v.y = roundtf(v.y); }
                long long ro = (long long)row * ldc;
                if (OUTPERM) {
                    C[ro + permcol(col)]     = v.x;
                    C[ro + permcol(col + 1)] = v.y;
                } else {
                    if (EPI == 2) {
                        float2 old = *(const float2*)(C + ro + col);
                        v.x += old.x; v.y += old.y;
                    }
                    *(float2*)(C + ro + col) = v;
                }
            }
        }
    }
}

// =====================================================================
// Fused flash attention (tf32, pre-rounded QKV -> no cvt on Q/K/V/P).
// One CTA per (q-tile 128, b*H+h); KV tile 128 (8 j-iterations).
// Output written block-permuted (feeds Wo GEMM APERM path).
// =====================================================================
#define KST 68
#define VST 72
#define PST 132
#define FKSZ (128*KST*4)
#define FVSZ (128*VST*4)
#define FL_SMEM (2*FKSZ + 2*FVSZ + 128*PST*4)

__global__ void __launch_bounds__(256, 1)
flash_kernel(const float* __restrict__ qkv, float* __restrict__ o)
{
    extern __shared__ char fs[];
    const int tid = threadIdx.x;
    const int w = tid >> 5, lane = tid & 31;
    const int g = lane >> 2, tg = lane & 3;
    const int qt = blockIdx.x;
    const int z  = blockIdx.y;
    const int bb = z >> 3, hh = z & 7;

    char* Ks = fs;
    char* Vs = fs + 2 * FKSZ;
    float* Ps = (float*)(fs + 2 * FKSZ + 2 * FVSZ);
    const uint32_t Ksb = smem_u32(Ks), Vsb = smem_u32(Vs);

    const float* qbase = qkv + (size_t)bb * SS * (3 * EE) + hh * DH;

    uint32_t qfr[8][4];
    {
        int r0 = qt * 128 + w * 16 + g;
        const float* q0 = qbase + (size_t)r0 * (3 * EE);
        const float* q1 = q0 + (size_t)8 * (3 * EE);
        #pragma unroll
        for (int kk = 0; kk < 8; kk++) {
            qfr[kk][0] = __float_as_uint(0.125f * q0[kk * 8 + tg]);
            qfr[kk][1] = __float_as_uint(0.125f * q1[kk * 8 + tg]);
            qfr[kk][2] = __float_as_uint(0.125f * q0[kk * 8 + tg + 4]);
            qfr[kk][3] = __float_as_uint(0.125f * q1[kk * 8 + tg + 4]);
        }
    }

    float m0 = -1e30f, m1 = -1e30f, l0 = 0.f, l1 = 0.f;
    float oacc[8][4];
    #pragma unroll
    for (int i = 0; i < 8; i++)
        #pragma unroll
        for (int q = 0; q < 4; q++) oacc[i][q] = 0.f;

    auto loadKV = [&](int st, int j) {
        const float* kg = qbase + EE     + (size_t)(j * 128) * (3 * EE);
        const float* vg = qbase + 2 * EE + (size_t)(j * 128) * (3 * EE);
        #pragma unroll
        for (int i = 0; i < 8; i++) {
            int idx = tid + i * 256;
            int row = idx >> 4, c4 = (idx & 15) * 4;
            cpasync16(Ksb + st * FKSZ + (row * KST + c4) * 4,
                      kg + (size_t)row * (3 * EE) + c4);
            cpasync16(Vsb + st * FVSZ + (row * VST + c4) * 4,
                      vg + (size_t)row * (3 * EE) + c4);
        }
    };

    loadKV(0, 0); cp_commit();

    const int prow0 = (w * 16 + g) * PST;
    const int prow1 = prow0 + 8 * PST;

    for (int j = 0; j < 8; j++) {
        cp_wait0();
        __syncthreads();
        if (j + 1 < 8) { loadKV((j + 1) & 1, j + 1); cp_commit(); }

        // ---- S = Q K^T ----
        float sacc[16][4];
        #pragma unroll
        for (int na = 0; na < 16; na++)
            #pragma unroll
            for (int q = 0; q < 4; q++) sacc[na][q] = 0.f;

        const float* Kt = (const float*)(Ks + (j & 1) * FKSZ);
        #pragma unroll
        for (int kk = 0; kk < 8; kk++) {
            #pragma unroll
            for (int na = 0; na < 16; na++) {
                int rn = na * 8 + g;
                uint32_t bfr[2];
                bfr[0] = __float_as_uint(Kt[rn * KST + kk * 8 + tg]);
                bfr[1] = __float_as_uint(Kt[rn * KST + kk * 8 + tg + 4]);
                mma_tf32(sacc[na], qfr[kk], bfr);
            }
        }

        // ---- online softmax; P stored tf32-rounded ----
        float mx0 = -1e30f, mx1 = -1e30f;
        #pragma unroll
        for (int na = 0; na < 16; na++) {
            mx0 = fmaxf(mx0, fmaxf(sacc[na][0], sacc[na][1]));
            mx1 = fmaxf(mx1, fmaxf(sacc[na][2], sacc[na][3]));
        }
        mx0 = fmaxf(mx0, __shfl_xor_sync(0xffffffffu, mx0, 1));
        mx0 = fmaxf(mx0, __shfl_xor_sync(0xffffffffu, mx0, 2));
        mx1 = fmaxf(mx1, __shfl_xor_sync(0xffffffffu, mx1, 1));
        mx1 = fmaxf(mx1, __shfl_xor_sync(0xffffffffu, mx1, 2));
        float nm0 = fmaxf(m0, mx0), nm1 = fmaxf(m1, mx1);
        float a0 = expf(m0 - nm0), a1 = expf(m1 - nm1);
        float rs0 = 0.f, rs1 = 0.f;
        #pragma unroll
        for (int na = 0; na < 16; na++) {
            float p00 = expf(sacc[na][0] - nm0);
            float p01 = expf(sacc[na][1] - nm0);
            float p10 = expf(sacc[na][2] - nm1);
            float p11 = expf(sacc[na][3] - nm1);
            rs0 += p00 + p01; rs1 += p10 + p11;
            int col = na * 8 + tg * 2;
            *(float2*)(Ps + prow0 + col) = make_float2(roundtf(p00), roundtf(p01));
            *(float2*)(Ps + prow1 + col) = make_float2(roundtf(p10), roundtf(p11));
        }
        rs0 += __shfl_xor_sync(0xffffffffu, rs0, 1);
        rs0 += __shfl_xor_sync(0xffffffffu, rs0, 2);
        rs1 += __shfl_xor_sync(0xffffffffu, rs1, 1);
        rs1 += __shfl_xor_sync(0xffffffffu, rs1, 2);
        l0 = l0 * a0 + rs0; l1 = l1 * a1 + rs1;
        m0 = nm0; m1 = nm1;
        #pragma unroll
        for (int na2 = 0; na2 < 8; na2++) {
            oacc[na2][0] *= a0; oacc[na2][1] *= a0;
            oacc[na2][2] *= a1; oacc[na2][3] *= a1;
        }
        __syncthreads();

        // ---- O += P V (all raw bit loads, no cvt) ----
        const float* Vt = (const float*)(Vs + (j & 1) * FVSZ);
        #pragma unroll
        for (int kk = 0; kk < 16; kk++) {
            uint32_t pf[4];
            pf[0] = __float_as_uint(Ps[prow0 + kk * 8 + tg]);
            pf[1] = __float_as_uint(Ps[prow1 + kk * 8 + tg]);
            pf[2] = __float_as_uint(Ps[prow0 + kk * 8 + tg + 4]);
            pf[3] = __float_as_uint(Ps[prow1 + kk * 8 + tg + 4]);
            #pragma unroll
            for (int na2 = 0; na2 < 8; na2++) {
                uint32_t bf[2];
                bf[0] = __float_as_uint(Vt[(kk * 8 + tg) * VST + na2 * 8 + g]);
                bf[1] = __float_as_uint(Vt[(kk * 8 + tg + 4) * VST + na2 * 8 + g]);
                mma_tf32(oacc[na2], pf, bf);
            }
        }
    }

    // ---- epilogue: O / l -> gmem, rounded + block-permuted ----
    float inv0 = 1.f / l0, inv1 = 1.f / l1;
    int r0 = qt * 128 + w * 16 + g;
    float* ob0 = o + (size_t)(bb * SS + r0) * EE + hh * DH;
    float* ob1 = ob0 + (size_t)8 * EE;
    #pragma unroll
    for (int na2 = 0; na2 < 8; na2++) {
        int col = na2 * 8 + tg * 2;
        ob0[permcol(col)]     = roundtf(oacc[na2][0] * inv0);
        ob0[permcol(col + 1)] = roundtf(oacc[na2][1] * inv0);
        ob1[permcol(col)]     = roundtf(oacc[na2][2] * inv1);
        ob1[permcol(col + 1)] = roundtf(oacc[na2][3] * inv1);
    }
}

// =====================================================================
// LayerNorm over last dim (512). Output tf32-rounded, block-permuted
// (feeds APERM GEMMs only).
// =====================================================================
__global__ void ln_kernel(const float* __restrict__ x, const float* __restrict__ g,
                          const float* __restrict__ b, float* __restrict__ y)
{
    long long row = blockIdx.x;
    const float* xr = x + row * EE;
    int tid = threadIdx.x;
    float4 v = *(const float4*)(xr + tid * 4);
    float s  = v.x + v.y + v.z + v.w;
    float s2 = v.x * v.x + v.y * v.y + v.z * v.z + v.w * v.w;
    #pragma unroll
    for (int o = 16; o > 0; o >>= 1) {
        s  += __shfl_xor_sync(0xffffffffu, s, o);
        s2 += __shfl_xor_sync(0xffffffffu, s2, o);
    }
    __shared__ float ss[4], ssq[4];
    int w = tid >> 5, l = tid & 31;
    if (l == 0) { ss[w] = s; ssq[w] = s2; }
    __syncthreads();
    s  = ss[0] + ss[1] + ss[2] + ss[3];
    s2 = ssq[0] + ssq[1] + ssq[2] + ssq[3];
    float m   = s * (1.0f / EE);
    float var = s2 * (1.0f / EE) - m * m;
    float inv = rsqrtf(var + 1e-5f);
    float4 gg = *(const float4*)(g + tid * 4);
    float4 bb = *(const float4*)(b + tid * 4);
    // cols 4t..4t+3 -> permuted positions base + {0,8,16,24}
    float* yr = y + row * EE + (tid >> 3) * 32 + (tid & 7);
    yr[0]  = roundtf((v.x - m) * inv * gg.x + bb.x);
    yr[8]  = roundtf((v.y - m) * inv * gg.y + bb.y);
    yr[16] = roundtf((v.z - m) * inv * gg.z + bb.z);
    yr[24] = roundtf((v.w - m) * inv * gg.w + bb.w);
}

// =====================================================================
// Mamba-style recurrence (4-way split accumulators; original f32 Wi2h).
// =====================================================================
__global__ void __cluster_dims__(8, 1, 1) __launch_bounds__(256, 1)
recur_kernel(const float* __restrict__ XP, const float* __restrict__ h0,
             const float* __restrict__ Wi2h, float* __restrict__ hout)
{
    __shared__ float hbuf[2 * EE];
    __shared__ float partial[256];

    const int tid = threadIdx.x;
    const int b = blockIdx.x >> 3;
    const int r = blockIdx.x & 7;
    const int part = tid >> 6;
    const int e    = tid & 63;

    float4 w[32];
    {
        const float* wsrc = Wi2h + (long long)(r * 64 + e) * (2 * EE) + EE + part * 128;
        #pragma unroll
        for (int i = 0; i < 32; i++) w[i] = *(const float4*)(wsrc + i * 4);
    }
    if (tid < 128) *(float4*)(hbuf + tid * 4) = *(const float4*)(h0 + b * EE + tid * 4);

    uint32_t hb = (uint32_t)__cvta_generic_to_shared(hbuf);
    __syncthreads();
    asm volatile("barrier.cluster.arrive.aligned;" ::: "memory");
    asm volatile("barrier.cluster.wait.aligned;"   ::: "memory");

    const long long xpbase = (long long)b * SS * EE + r * 64 + e;

    for (int t = 0; t < SS; t++) {
        float xpv = 0.f;
        if (tid < 64) xpv = __ldg(XP + xpbase + (long long)t * EE);

        const float* hr = hbuf + (t & 1) * EE + part * 128;
        float a0 = 0.f, a1 = 0.f, a2 = 0.f, a3 = 0.f;
        #pragma unroll
        for (int i = 0; i < 32; i++) {
            float4 h4 = *(const float4*)(hr + i * 4);
            a0 += w[i].x * h4.x; a1 += w[i].y * h4.y;
            a2 += w[i].z * h4.z; a3 += w[i].w * h4.w;
        }
        partial[part * 64 + e] = (a0 + a1) + (a2 + a3);
        __syncthreads();

        if (tid < 64) {
            float sm = partial[e] + partial[64 + e] + partial[128 + e] + partial[192 + e] + xpv;
            float hn = tanhf(sm);
            hn = (hn > 0.f) ? hn : 0.f;
            uint32_t loff = hb + (uint32_t)((((t + 1) & 1) * EE + r * 64 + e) * 4);
            #pragma unroll
            for (int c = 0; c < 8; c++) {
                uint32_t ra;
                asm("mapa.shared::cluster.u32 %0, %1, %2;" : "=r"(ra) : "r"(loff), "r"(c));
                asm volatile("st.shared::cluster.f32 [%0], %1;" :: "r"(ra), "f"(hn));
            }
        }
        asm volatile("barrier.cluster.arrive.aligned;" ::: "memory");
        asm volatile("barrier.cluster.wait.aligned;"   ::: "memory");
    }
    if (tid < 64) hout[b * EE + r * 64 + e] = hbuf[r * 64 + e];
}

// =====================================================================
// Head (unchanged).
// =====================================================================
__global__ void head_kernel(const float* __restrict__ hfin, const float* __restrict__ Wh2o,
                            const float* __restrict__ bh2o, const float* __restrict__ Wc,
                            const float* __restrict__ bc, float* __restrict__ out, int half)
{
    int b = blockIdx.x, tid = threadIdx.x;
    __shared__ float hrow[EE];
    __shared__ float red[EE];
    hrow[tid] = hfin[b * EE + tid];
    __syncthreads();
    const float* wr = Wh2o + (long long)tid * EE;
    float acc = bh2o[tid];
    #pragma unroll 8
    for (int f = 0; f < EE; f += 4) {
        float4 w4 = *(const float4*)(wr + f);
        acc += w4.x * hrow[f] + w4.y * hrow[f + 1] + w4.z * hrow[f + 2] + w4.w * hrow[f + 3];
    }
    red[tid] = acc * Wc[tid];
    __syncthreads();
    for (int s = 256; s > 0; s >>= 1) {
        if (tid < s) red[tid] += red[tid + s];
        __syncthreads();
    }
    if (tid == 0) {
        float lg = red[0] + bc[0];
        out[b] = lg;
        out[half + b] = 1.f / (1.f + expf(-lg));
    }
}

// ---------------- host-side launch helpers ----------------
template<int EPI, bool APERM, bool RND, bool OUTPERM>
static void run_mm(const float* A, const float* B, const float* bias, float* C,
                   int M, int N, int K, int lda, int ldb, int ldc)
{
    cudaFuncSetAttribute(gemm_mma<EPI, APERM, RND, OUTPERM>,
                         cudaFuncAttributeMaxDynamicSharedMemorySize, GEMM_SMEM);
    dim3 grid(N / 128, M / 128, 1);
    gemm_mma<EPI, APERM, RND, OUTPERM><<<grid, 256, GEMM_SMEM>>>(A, B, bias, C,
                                                                 M, N, K, lda, ldb, ldc);
}

static void run_perm(const float* src, float* dst, int n)
{
    permute_round_kernel<<<(n + 255) / 256, 256>>>(src, dst, n);
}

extern "C" void kernel_launch(void* const* d_in, const int* in_sizes, int n_in,
                              void* d_out, int out_size)
{
    const float* bm   = (const float*)d_in[0];
    const float* h0   = (const float*)d_in[1];
    const float* Wp   = (const float*)d_in[2];
    const float* bp   = (const float*)d_in[3];
    const float* ln1g = (const float*)d_in[4];
    const float* ln1b = (const float*)d_in[5];
    const float* Wqkv = (const float*)d_in[6];
    const float* bqkv = (const float*)d_in[7];
    const float* Wo   = (const float*)d_in[8];
    const float* bo   = (const float*)d_in[9];
    const float* ln2g = (const float*)d_in[10];
    const float* ln2b = (const float*)d_in[11];
    const float* W1   = (const float*)d_in[12];
    const float* b1   = (const float*)d_in[13];
    const float* W2   = (const float*)d_in[14];
    const float* b2   = (const float*)d_in[15];
    const float* Wi2h = (const float*)d_in[16];
    const float* bi2h = (const float*)d_in[17];
    const float* Wh2o = (const float*)d_in[18];
    const float* bh2o = (const float*)d_in[19];
    const float* Wc   = (const float*)d_in[20];
    const float* bc   = (const float*)d_in[21];
    float* out = (float*)d_out;

    float *px, *pa, *pq, *po, *pf, *pxp, *ph, *pw;
    cudaGetSymbolAddress((void**)&px,  g_x);
    cudaGetSymbolAddress((void**)&pa,  g_a);
    cudaGetSymbolAddress((void**)&pq,  g_qkv);
    cudaGetSymbolAddress((void**)&po,  g_o);
    cudaGetSymbolAddress((void**)&pf,  g_f);
    cudaGetSymbolAddress((void**)&pxp, g_xp);
    cudaGetSymbolAddress((void**)&ph,  g_h);
    cudaGetSymbolAddress((void**)&pw,  g_wr);

    cudaFuncSetAttribute(flash_kernel,
                         cudaFuncAttributeMaxDynamicSharedMemorySize, FL_SMEM);

    // 0) pre-permute+round all weights
    run_perm(Wp,   pw + OFF_WP,   EE * DIN);
    run_perm(Wqkv, pw + OFF_WQKV, LL * 3 * EE * EE);
    run_perm(Wo,   pw + OFF_WO,   LL * EE * EE);
    run_perm(W1,   pw + OFF_W1,   LL * FF * EE);
    run_perm(W2,   pw + OFF_W2,   LL * EE * FF);
    run_perm(Wi2h, pw + OFF_WI,   EE * 2 * EE);

    // 1) modality projection (A raw -> scalar+cvt; out = residual f32)
    run_mm<0, false, false, false>(bm, pw + OFF_WP, bp, px, MTOK, EE, DIN, DIN, DIN, EE);

    for (int l = 0; l < LL; l++) {
        const float* wqkv = pw + OFF_WQKV + (size_t)l * 3 * EE * EE;
        const float* bqk  = bqkv + (size_t)l * 3 * EE;
        const float* wo   = pw + OFF_WO + (size_t)l * EE * EE;
        const float* bo_  = bo   + (size_t)l * EE;
        const float* w1   = pw + OFF_W1 + (size_t)l * FF * EE;
        const float* b1_  = b1   + (size_t)l * FF;
        const float* w2   = pw + OFF_W2 + (size_t)l * EE * FF;
        const float* b2_  = b2   + (size_t)l * EE;

        // pre-LN attention (LN output rounded+permuted)
        ln_kernel<<<MTOK, 128>>>(px, ln1g + l * EE, ln1b + l * EE, pa);
        // QKV: A permuted; output standard rounded (feeds flash)
        run_mm<0, true, true, false>(pa, wqkv, bqk, pq, MTOK, 3 * EE, EE, EE, EE, 3 * EE);

        // fused flash attention: qkv -> o (rounded + permuted out)
        {
            dim3 grid(SS / 128, BB * HH);
            flash_kernel<<<grid, 256, FL_SMEM>>>(pq, po);
        }

        // x += O @ Wo^T + bo (A permuted; residual f32 out)
        run_mm<2, true, false, false>(po, wo, bo_, px, MTOK, EE, EE, EE, EE, EE);

        // pre-LN FFN
        ln_kernel<<<MTOK, 128>>>(px, ln2g + l * EE, ln2b + l * EE, pa);
        // FFN1: A permuted; gelu out rounded+permuted (feeds FFN2)
        run_mm<1, true, true, true>(pa, w1, b1_, pf, MTOK, FF, EE, EE, EE, FF);
        // FFN2: A permuted; residual f32 out
        run_mm<2, true, false, false>(pf, w2, b2_, px, MTOK, EE, FF, FF, FF, EE);
    }

    // recurrence x-part (A = raw residual -> scalar+cvt)
    run_mm<0, false, false, false>(px, pw + OFF_WI, bi2h, pxp, MTOK, EE, EE, EE, 2 * EE, EE);

    // sequential recurrence (persistent, clustered; original f32 Wi2h)
    recur_kernel<<<128, 256>>>(pxp, h0, Wi2h, ph);

    // head: logits + sigmoid
    head_kernel<<<BB, 512>>>(ph, Wh2o, bh2o, Wc, bc, out, out_size / 2);
}

// round 11
// speedup vs baseline: 1.0985x; 1.0985x over previous
#include <cuda_runtime.h>
#include <cuda_bf16.h>
#include <math.h>
#include <stdint.h>

// ---------------- problem constants ----------------
#define BB   16
#define SS   1024
#define DIN  768
#define EE   512
#define HH   8
#define LL   2
#define FF   2048
#define DH   64
#define MTOK (BB*SS)          // 16384 rows

// ---------------- scratch ----------------
__device__ float g_x  [MTOK*EE];
__device__ float g_a  [MTOK*EE];
__device__ float g_qkv[MTOK*3*EE];
__device__ float g_o  [MTOK*EE];
__device__ float g_f  [MTOK*FF];
__device__ float g_xp [MTOK*EE];
__device__ float g_h  [BB*EE];
__device__ float g_wr [7208960];        // block-permuted + tf32-rounded weights

// rounded-weight offsets
#define OFF_WP   0
#define OFF_WQKV 393216
#define OFF_WO   1966080
#define OFF_W1   2490368
#define OFF_W2   4587520
#define OFF_WI   6684672

// ---------------- helpers ----------------
__device__ __forceinline__ float gelu_exact(float x) {
    return 0.5f * x * (1.0f + erff(x * 0.7071067811865476f));
}
__device__ __forceinline__ void cpasync16(uint32_t dst, const void* src) {
    asm volatile("cp.async.cg.shared.global [%0], [%1], 16;" :: "r"(dst), "l"(src));
}
__device__ __forceinline__ void cp_commit() { asm volatile("cp.async.commit_group;"); }
__device__ __forceinline__ void cp_wait1() { asm volatile("cp.async.wait_group 1;"); }
__device__ __forceinline__ void cp_wait0() { asm volatile("cp.async.wait_group 0;"); }
__device__ __forceinline__ uint32_t smem_u32(const void* p) {
    uint32_t a;
    asm("{ .reg .u64 t; cvta.to.shared.u64 t, %1; cvt.u32.u64 %0, t; }" : "=r"(a) : "l"(p));
    return a;
}
__device__ __forceinline__ uint32_t f2tf(float f) {
    uint32_t u;
    asm("cvt.rna.tf32.f32 %0, %1;" : "=r"(u) : "f"(f));
    return u;
}
__device__ __forceinline__ float roundtf(float f) {
    return __uint_as_float(f2tf(f));
}
__device__ __forceinline__ void mma_tf32(float* c, const uint32_t* a, const uint32_t* b) {
    asm volatile(
        "mma.sync.aligned.m16n8k8.row.col.f32.tf32.tf32.f32 "
        "{%0,%1,%2,%3}, {%4,%5,%6,%7}, {%8,%9}, {%0,%1,%2,%3};"
        : "+f"(c[0]), "+f"(c[1]), "+f"(c[2]), "+f"(c[3])
        : "r"(a[0]), "r"(a[1]), "r"(a[2]), "r"(a[3]), "r"(b[0]), "r"(b[1]));
}

// =====================================================================
// Weight prep: block-32 permute + tf32 round.
// dst position p (within 32-block): src k = (p>>3) + (p&7)*4.
// So dst holds, contiguously, the 8 values with k%4 == p>>3 — exactly one
// thread's B-fragment set for a 32-K chunk.
// =====================================================================
__global__ void permute_round_kernel(const float* __restrict__ src,
                                     float* __restrict__ dst, int n)
{
    int i = blockIdx.x * 256 + threadIdx.x;
    if (i >= n) return;
    int p = i & 31;
    int base = i - p;
    dst[i] = roundtf(src[base + (p >> 3) + ((p & 7) << 2)]);
}

// =====================================================================
// tf32 warp-MMA GEMM: C[M,N] = epi( A[M,K] * B^T + bias )
//   B: block-permuted tf32 weights (g_wr) -> 2x LDS.128 per frag row.
//   A: STANDARD layout; scalar frag loads; ACVT adds cvt (raw f32 A).
//   RND: tf32-round outputs. EPI: 0=bias, 1=bias+gelu, 2=C += acc+bias.
//   SMEM rows padded to 36 floats (144B) -> conflict-free frag loads.
// =====================================================================
#define ROWB 144
#define ASTG (128*ROWB)
#define STGS (2*ASTG)
static const int GEMM_SMEM = 3 * STGS;   // 110592

template<int EPI, bool ACVT, bool RND>
__global__ void __launch_bounds__(256, 2)
gemm_mma(const float* __restrict__ A, const float* __restrict__ B,
         const float* __restrict__ bias, float* __restrict__ C,
         int M, int N, int K, int lda, int ldb, int ldc)
{
    extern __shared__ char smem[];
    const uint32_t sb = smem_u32(smem);

    const int tid = threadIdx.x;
    const int wid = tid >> 5;
    const int lane = tid & 31;
    const int g  = lane >> 2;
    const int tg = lane & 3;
    const int wm = wid & 3;
    const int wn = wid >> 2;
    const int bm = blockIdx.y * 128;
    const int bn = blockIdx.x * 128;

    const int NC = K >> 5;

    float acc[2][8][4];
    #pragma unroll
    for (int i = 0; i < 2; i++)
        #pragma unroll
        for (int j = 0; j < 8; j++)
            #pragma unroll
            for (int q = 0; q < 4; q++) acc[i][j][q] = 0.f;

    auto loadA = [&](int stage, int k0) {
        uint32_t base = sb + stage * STGS;
        const float* src0 = A + (long long)bm * lda + k0;
        #pragma unroll
        for (int i = 0; i < 4; i++) {
            int j = tid + i * 256;
            int row = j >> 3;
            int c4  = (j & 7) * 4;
            cpasync16(base + row * ROWB + c4 * 4,
                      src0 + (long long)row * lda + c4);
        }
    };
    auto loadB = [&](int stage, int k0) {
        uint32_t base = sb + stage * STGS + ASTG;
        const float* src0 = B + (long long)bn * ldb + k0;
        #pragma unroll
        for (int i = 0; i < 4; i++) {
            int j = tid + i * 256;
            int row = j >> 3;
            int c4  = (j & 7) * 4;
            cpasync16(base + row * ROWB + c4 * 4,
                      src0 + (long long)row * ldb + c4);
        }
    };

    auto compute = [&](int stage) {
        const char* Ab = smem + stage * STGS;
        const char* Bb = Ab + ASTG;
        // A fragments for the whole chunk: 4 rows x 8 values (k = tg + 4j),
        // scalar loads from STANDARD row layout (conflict-free).
        uint32_t af[4][8];
        #pragma unroll
        for (int rr = 0; rr < 4; rr++) {
            int row = wm * 32 + rr * 8 + g;
            #pragma unroll
            for (int jj = 0; jj < 8; jj++) {
                float v = *(const float*)(Ab + row * ROWB + (tg + 4 * jj) * 4);
                af[rr][jj] = ACVT ? f2tf(v) : __float_as_uint(v);
            }
        }
        #pragma unroll
        for (int na = 0; na < 8; na++) {
            int rn = wn * 64 + na * 8 + g;
            // permuted B row: this thread's 8 frag values are contiguous
            float4 b0 = *(const float4*)(Bb + rn * ROWB + tg * 32);
            float4 b1 = *(const float4*)(Bb + rn * ROWB + tg * 32 + 16);
            uint32_t bf[8];
            bf[0] = __float_as_uint(b0.x); bf[1] = __float_as_uint(b0.y);
            bf[2] = __float_as_uint(b0.z); bf[3] = __float_as_uint(b0.w);
            bf[4] = __float_as_uint(b1.x); bf[5] = __float_as_uint(b1.y);
            bf[6] = __float_as_uint(b1.z); bf[7] = __float_as_uint(b1.w);
            #pragma unroll
            for (int ma = 0; ma < 2; ma++)
                #pragma unroll
                for (int kk = 0; kk < 4; kk++) {
                    uint32_t a[4] = {af[ma * 2][2 * kk], af[ma * 2 + 1][2 * kk],
                                     af[ma * 2][2 * kk + 1], af[ma * 2 + 1][2 * kk + 1]};
                    mma_tf32(acc[ma][na], a, bf + 2 * kk);
                }
        }
    };

    // ---------- 3-stage pipelined mainloop ----------
    loadA(0, 0); loadB(0, 0); cp_commit();
    loadA(1, 32); loadB(1, 32); cp_commit();
    for (int c = 0; c < NC; c++) {
        if (c + 1 < NC) cp_wait1(); else cp_wait0();
        __syncthreads();
        if (c + 2 < NC) {
            int s = (c + 2) % 3;
            loadA(s, (c + 2) << 5); loadB(s, (c + 2) << 5); cp_commit();
        }
        compute(c % 3);
    }

    // ---------- epilogue (standard layout, coalesced float2) ----------
    #pragma unroll
    for (int ma = 0; ma < 2; ma++) {
        int row0 = bm + wm * 32 + ma * 16 + g;
        #pragma unroll
        for (int na = 0; na < 8; na++) {
            int col = bn + wn * 64 + na * 8 + tg * 2;
            #pragma unroll
            for (int half = 0; half < 2; half++) {
                int row = row0 + half * 8;
                float2 v;
                v.x = acc[ma][na][half * 2 + 0];
                v.y = acc[ma][na][half * 2 + 1];
                if (bias) { v.x += bias[col]; v.y += bias[col + 1]; }
                if (EPI == 1) { v.x = gelu_exact(v.x); v.y = gelu_exact(v.y); }
                if (RND) { v.x = roundtf(v.x); v.y = roundtf(v.y); }
                long long ro = (long long)row * ldc;
                if (EPI == 2) {
                    float2 old = *(const float2*)(C + ro + col);
                    v.x += old.x; v.y += old.y;
                }
                *(float2*)(C + ro + col) = v;
            }
        }
    }
}

// =====================================================================
// Fused flash attention (tf32, pre-rounded QKV -> no cvt on Q/K/V/P).
// One CTA per (q-tile 128, b*H+h); KV tile 128 (8 j-iterations).
// STANDARD rounded output (feeds Wo GEMM's raw-bit A path).
// =====================================================================
#define KST 68
#define VST 72
#define PST 132
#define FKSZ (128*KST*4)
#define FVSZ (128*VST*4)
#define FL_SMEM (2*FKSZ + 2*FVSZ + 128*PST*4)

__global__ void __launch_bounds__(256, 1)
flash_kernel(const float* __restrict__ qkv, float* __restrict__ o)
{
    extern __shared__ char fs[];
    const int tid = threadIdx.x;
    const int w = tid >> 5, lane = tid & 31;
    const int g = lane >> 2, tg = lane & 3;
    const int qt = blockIdx.x;
    const int z  = blockIdx.y;
    const int bb = z >> 3, hh = z & 7;

    char* Ks = fs;
    char* Vs = fs + 2 * FKSZ;
    float* Ps = (float*)(fs + 2 * FKSZ + 2 * FVSZ);
    const uint32_t Ksb = smem_u32(Ks), Vsb = smem_u32(Vs);

    const float* qbase = qkv + (size_t)bb * SS * (3 * EE) + hh * DH;

    uint32_t qfr[8][4];
    {
        int r0 = qt * 128 + w * 16 + g;
        const float* q0 = qbase + (size_t)r0 * (3 * EE);
        const float* q1 = q0 + (size_t)8 * (3 * EE);
        #pragma unroll
        for (int kk = 0; kk < 8; kk++) {
            qfr[kk][0] = __float_as_uint(0.125f * q0[kk * 8 + tg]);
            qfr[kk][1] = __float_as_uint(0.125f * q1[kk * 8 + tg]);
            qfr[kk][2] = __float_as_uint(0.125f * q0[kk * 8 + tg + 4]);
            qfr[kk][3] = __float_as_uint(0.125f * q1[kk * 8 + tg + 4]);
        }
    }

    float m0 = -1e30f, m1 = -1e30f, l0 = 0.f, l1 = 0.f;
    float oacc[8][4];
    #pragma unroll
    for (int i = 0; i < 8; i++)
        #pragma unroll
        for (int q = 0; q < 4; q++) oacc[i][q] = 0.f;

    auto loadKV = [&](int st, int j) {
        const float* kg = qbase + EE     + (size_t)(j * 128) * (3 * EE);
        const float* vg = qbase + 2 * EE + (size_t)(j * 128) * (3 * EE);
        #pragma unroll
        for (int i = 0; i < 8; i++) {
            int idx = tid + i * 256;
            int row = idx >> 4, c4 = (idx & 15) * 4;
            cpasync16(Ksb + st * FKSZ + (row * KST + c4) * 4,
                      kg + (size_t)row * (3 * EE) + c4);
            cpasync16(Vsb + st * FVSZ + (row * VST + c4) * 4,
                      vg + (size_t)row * (3 * EE) + c4);
        }
    };

    loadKV(0, 0); cp_commit();

    const int prow0 = (w * 16 + g) * PST;
    const int prow1 = prow0 + 8 * PST;

    for (int j = 0; j < 8; j++) {
        cp_wait0();
        __syncthreads();
        if (j + 1 < 8) { loadKV((j + 1) & 1, j + 1); cp_commit(); }

        // ---- S = Q K^T ----
        float sacc[16][4];
        #pragma unroll
        for (int na = 0; na < 16; na++)
            #pragma unroll
            for (int q = 0; q < 4; q++) sacc[na][q] = 0.f;

        const float* Kt = (const float*)(Ks + (j & 1) * FKSZ);
        #pragma unroll
        for (int kk = 0; kk < 8; kk++) {
            #pragma unroll
            for (int na = 0; na < 16; na++) {
                int rn = na * 8 + g;
                uint32_t bfr[2];
                bfr[0] = __float_as_uint(Kt[rn * KST + kk * 8 + tg]);
                bfr[1] = __float_as_uint(Kt[rn * KST + kk * 8 + tg + 4]);
                mma_tf32(sacc[na], qfr[kk], bfr);
            }
        }

        // ---- online softmax; P stored tf32-rounded (raw reload later) ----
        float mx0 = -1e30f, mx1 = -1e30f;
        #pragma unroll
        for (int na = 0; na < 16; na++) {
            mx0 = fmaxf(mx0, fmaxf(sacc[na][0], sacc[na][1]));
            mx1 = fmaxf(mx1, fmaxf(sacc[na][2], sacc[na][3]));
        }
        mx0 = fmaxf(mx0, __shfl_xor_sync(0xffffffffu, mx0, 1));
        mx0 = fmaxf(mx0, __shfl_xor_sync(0xffffffffu, mx0, 2));
        mx1 = fmaxf(mx1, __shfl_xor_sync(0xffffffffu, mx1, 1));
        mx1 = fmaxf(mx1, __shfl_xor_sync(0xffffffffu, mx1, 2));
        float nm0 = fmaxf(m0, mx0), nm1 = fmaxf(m1, mx1);
        float a0 = expf(m0 - nm0), a1 = expf(m1 - nm1);
        float rs0 = 0.f, rs1 = 0.f;
        #pragma unroll
        for (int na = 0; na < 16; na++) {
            float p00 = expf(sacc[na][0] - nm0);
            float p01 = expf(sacc[na][1] - nm0);
            float p10 = expf(sacc[na][2] - nm1);
            float p11 = expf(sacc[na][3] - nm1);
            rs0 += p00 + p01; rs1 += p10 + p11;
            int col = na * 8 + tg * 2;
            *(float2*)(Ps + prow0 + col) = make_float2(roundtf(p00), roundtf(p01));
            *(float2*)(Ps + prow1 + col) = make_float2(roundtf(p10), roundtf(p11));
        }
        rs0 += __shfl_xor_sync(0xffffffffu, rs0, 1);
        rs0 += __shfl_xor_sync(0xffffffffu, rs0, 2);
        rs1 += __shfl_xor_sync(0xffffffffu, rs1, 1);
        rs1 += __shfl_xor_sync(0xffffffffu, rs1, 2);
        l0 = l0 * a0 + rs0; l1 = l1 * a1 + rs1;
        m0 = nm0; m1 = nm1;
        #pragma unroll
        for (int na2 = 0; na2 < 8; na2++) {
            oacc[na2][0] *= a0; oacc[na2][1] *= a0;
            oacc[na2][2] *= a1; oacc[na2][3] *= a1;
        }
        __syncthreads();

        // ---- O += P V (all raw bit loads, no cvt) ----
        const float* Vt = (const float*)(Vs + (j & 1) * FVSZ);
        #pragma unroll
        for (int kk = 0; kk < 16; kk++) {
            uint32_t pf[4];
            pf[0] = __float_as_uint(Ps[prow0 + kk * 8 + tg]);
            pf[1] = __float_as_uint(Ps[prow1 + kk * 8 + tg]);
            pf[2] = __float_as_uint(Ps[prow0 + kk * 8 + tg + 4]);
            pf[3] = __float_as_uint(Ps[prow1 + kk * 8 + tg + 4]);
            #pragma unroll
            for (int na2 = 0; na2 < 8; na2++) {
                uint32_t bf[2];
                bf[0] = __float_as_uint(Vt[(kk * 8 + tg) * VST + na2 * 8 + g]);
                bf[1] = __float_as_uint(Vt[(kk * 8 + tg + 4) * VST + na2 * 8 + g]);
                mma_tf32(oacc[na2], pf, bf);
            }
        }
    }

    // ---- epilogue: O / l -> gmem, rounded, STANDARD layout ----
    float inv0 = 1.f / l0, inv1 = 1.f / l1;
    int r0 = qt * 128 + w * 16 + g;
    float* ob0 = o + (size_t)(bb * SS + r0) * EE + hh * DH;
    float* ob1 = ob0 + (size_t)8 * EE;
    #pragma unroll
    for (int na2 = 0; na2 < 8; na2++) {
        int col = na2 * 8 + tg * 2;
        *(float2*)(ob0 + col) = make_float2(roundtf(oacc[na2][0] * inv0),
                                            roundtf(oacc[na2][1] * inv0));
        *(float2*)(ob1 + col) = make_float2(roundtf(oacc[na2][2] * inv1),
                                            roundtf(oacc[na2][3] * inv1));
    }
}

// =====================================================================
// LayerNorm over last dim (512). Output tf32-rounded, STANDARD layout.
// =====================================================================
__global__ void ln_kernel(const float* __restrict__ x, const float* __restrict__ g,
                          const float* __restrict__ b, float* __restrict__ y)
{
    long long row = blockIdx.x;
    const float* xr = x + row * EE;
    int tid = threadIdx.x;
    float4 v = *(const float4*)(xr + tid * 4);
    float s  = v.x + v.y + v.z + v.w;
    float s2 = v.x * v.x + v.y * v.y + v.z * v.z + v.w * v.w;
    #pragma unroll
    for (int o = 16; o > 0; o >>= 1) {
        s  += __shfl_xor_sync(0xffffffffu, s, o);
        s2 += __shfl_xor_sync(0xffffffffu, s2, o);
    }
    __shared__ float ss[4], ssq[4];
    int w = tid >> 5, l = tid & 31;
    if (l == 0) { ss[w] = s; ssq[w] = s2; }
    __syncthreads();
    s  = ss[0] + ss[1] + ss[2] + ss[3];
    s2 = ssq[0] + ssq[1] + ssq[2] + ssq[3];
    float m   = s * (1.0f / EE);
    float var = s2 * (1.0f / EE) - m * m;
    float inv = rsqrtf(var + 1e-5f);
    float4 gg = *(const float4*)(g + tid * 4);
    float4 bb = *(const float4*)(b + tid * 4);
    float4 o4;
    o4.x = roundtf((v.x - m) * inv * gg.x + bb.x);
    o4.y = roundtf((v.y - m) * inv * gg.y + bb.y);
    o4.z = roundtf((v.z - m) * inv * gg.z + bb.z);
    o4.w = roundtf((v.w - m) * inv * gg.w + bb.w);
    *(float4*)(y + row * EE + tid * 4) = o4;
}

// =====================================================================
// Mamba-style recurrence (4-way split accumulators; original f32 Wi2h).
// =====================================================================
__global__ void __cluster_dims__(8, 1, 1) __launch_bounds__(256, 1)
recur_kernel(const float* __restrict__ XP, const float* __restrict__ h0,
             const float* __restrict__ Wi2h, float* __restrict__ hout)
{
    __shared__ float hbuf[2 * EE];
    __shared__ float partial[256];

    const int tid = threadIdx.x;
    const int b = blockIdx.x >> 3;
    const int r = blockIdx.x & 7;
    const int part = tid >> 6;
    const int e    = tid & 63;

    float4 w[32];
    {
        const float* wsrc = Wi2h + (long long)(r * 64 + e) * (2 * EE) + EE + part * 128;
        #pragma unroll
        for (int i = 0; i < 32; i++) w[i] = *(const float4*)(wsrc + i * 4);
    }
    if (tid < 128) *(float4*)(hbuf + tid * 4) = *(const float4*)(h0 + b * EE + tid * 4);

    uint32_t hb = (uint32_t)__cvta_generic_to_shared(hbuf);
    __syncthreads();
    asm volatile("barrier.cluster.arrive.aligned;" ::: "memory");
    asm volatile("barrier.cluster.wait.aligned;"   ::: "memory");

    const long long xpbase = (long long)b * SS * EE + r * 64 + e;

    for (int t = 0; t < SS; t++) {
        float xpv = 0.f;
        if (tid < 64) xpv = __ldg(XP + xpbase + (long long)t * EE);

        const float* hr = hbuf + (t & 1) * EE + part * 128;
        float a0 = 0.f, a1 = 0.f, a2 = 0.f, a3 = 0.f;
        #pragma unroll
        for (int i = 0; i < 32; i++) {
            float4 h4 = *(const float4*)(hr + i * 4);
            a0 += w[i].x * h4.x; a1 += w[i].y * h4.y;
            a2 += w[i].z * h4.z; a3 += w[i].w * h4.w;
        }
        partial[part * 64 + e] = (a0 + a1) + (a2 + a3);
        __syncthreads();

        if (tid < 64) {
            float sm = partial[e] + partial[64 + e] + partial[128 + e] + partial[192 + e] + xpv;
            float hn = tanhf(sm);
            hn = (hn > 0.f) ? hn : 0.f;
            uint32_t loff = hb + (uint32_t)((((t + 1) & 1) * EE + r * 64 + e) * 4);
            #pragma unroll
            for (int c = 0; c < 8; c++) {
                uint32_t ra;
                asm("mapa.shared::cluster.u32 %0, %1, %2;" : "=r"(ra) : "r"(loff), "r"(c));
                asm volatile("st.shared::cluster.f32 [%0], %1;" :: "r"(ra), "f"(hn));
            }
        }
        asm volatile("barrier.cluster.arrive.aligned;" ::: "memory");
        asm volatile("barrier.cluster.wait.aligned;"   ::: "memory");
    }
    if (tid < 64) hout[b * EE + r * 64 + e] = hbuf[r * 64 + e];
}

// =====================================================================
// Head (unchanged).
// =====================================================================
__global__ void head_kernel(const float* __restrict__ hfin, const float* __restrict__ Wh2o,
                            const float* __restrict__ bh2o, const float* __restrict__ Wc,
                            const float* __restrict__ bc, float* __restrict__ out, int half)
{
    int b = blockIdx.x, tid = threadIdx.x;
    __shared__ float hrow[EE];
    __shared__ float red[EE];
    hrow[tid] = hfin[b * EE + tid];
    __syncthreads();
    const float* wr = Wh2o + (long long)tid * EE;
    float acc = bh2o[tid];
    #pragma unroll 8
    for (int f = 0; f < EE; f += 4) {
        float4 w4 = *(const float4*)(wr + f);
        acc += w4.x * hrow[f] + w4.y * hrow[f + 1] + w4.z * hrow[f + 2] + w4.w * hrow[f + 3];
    }
    red[tid] = acc * Wc[tid];
    __syncthreads();
    for (int s = 256; s > 0; s >>= 1) {
        if (tid < s) red[tid] += red[tid + s];
        __syncthreads();
    }
    if (tid == 0) {
        float lg = red[0] + bc[0];
        out[b] = lg;
        out[half + b] = 1.f / (1.f + expf(-lg));
    }
}

// ---------------- host-side launch helpers ----------------
template<int EPI, bool ACVT, bool RND>
static void run_mm(const float* A, const float* B, const float* bias, float* C,
                   int M, int N, int K, int lda, int ldb, int ldc)
{
    cudaFuncSetAttribute(gemm_mma<EPI, ACVT, RND>,
                         cudaFuncAttributeMaxDynamicSharedMemorySize, GEMM_SMEM);
    dim3 grid(N / 128, M / 128, 1);
    gemm_mma<EPI, ACVT, RND><<<grid, 256, GEMM_SMEM>>>(A, B, bias, C, M, N, K, lda, ldb, ldc);
}

static void run_perm(const float* src, float* dst, int n)
{
    permute_round_kernel<<<(n + 255) / 256, 256>>>(src, dst, n);
}

extern "C" void kernel_launch(void* const* d_in, const int* in_sizes, int n_in,
                              void* d_out, int out_size)
{
    const float* bm   = (const float*)d_in[0];
    const float* h0   = (const float*)d_in[1];
    const float* Wp   = (const float*)d_in[2];
    const float* bp   = (const float*)d_in[3];
    const float* ln1g = (const float*)d_in[4];
    const float* ln1b = (const float*)d_in[5];
    const float* Wqkv = (const float*)d_in[6];
    const float* bqkv = (const float*)d_in[7];
    const float* Wo   = (const float*)d_in[8];
    const float* bo   = (const float*)d_in[9];
    const float* ln2g = (const float*)d_in[10];
    const float* ln2b = (const float*)d_in[11];
    const float* W1   = (const float*)d_in[12];
    const float* b1   = (const float*)d_in[13];
    const float* W2   = (const float*)d_in[14];
    const float* b2   = (const float*)d_in[15];
    const float* Wi2h = (const float*)d_in[16];
    const float* bi2h = (const float*)d_in[17];
    const float* Wh2o = (const float*)d_in[18];
    const float* bh2o = (const float*)d_in[19];
    const float* Wc   = (const float*)d_in[20];
    const float* bc   = (const float*)d_in[21];
    float* out = (float*)d_out;

    float *px, *pa, *pq, *po, *pf, *pxp, *ph, *pw;
    cudaGetSymbolAddress((void**)&px,  g_x);
    cudaGetSymbolAddress((void**)&pa,  g_a);
    cudaGetSymbolAddress((void**)&pq,  g_qkv);
    cudaGetSymbolAddress((void**)&po,  g_o);
    cudaGetSymbolAddress((void**)&pf,  g_f);
    cudaGetSymbolAddress((void**)&pxp, g_xp);
    cudaGetSymbolAddress((void**)&ph,  g_h);
    cudaGetSymbolAddress((void**)&pw,  g_wr);

    cudaFuncSetAttribute(flash_kernel,
                         cudaFuncAttributeMaxDynamicSharedMemorySize, FL_SMEM);

    // 0) pre-permute+round all weights
    run_perm(Wp,   pw + OFF_WP,   EE * DIN);
    run_perm(Wqkv, pw + OFF_WQKV, LL * 3 * EE * EE);
    run_perm(Wo,   pw + OFF_WO,   LL * EE * EE);
    run_perm(W1,   pw + OFF_W1,   LL * FF * EE);
    run_perm(W2,   pw + OFF_W2,   LL * EE * FF);
    run_perm(Wi2h, pw + OFF_WI,   EE * 2 * EE);

    // 1) modality projection (A raw f32 -> cvt; out = residual f32)
    run_mm<0, true, false>(bm, pw + OFF_WP, bp, px, MTOK, EE, DIN, DIN, DIN, EE);

    for (int l = 0; l < LL; l++) {
        const float* wqkv = pw + OFF_WQKV + (size_t)l * 3 * EE * EE;
        const float* bqk  = bqkv + (size_t)l * 3 * EE;
        const float* wo   = pw + OFF_WO + (size_t)l * EE * EE;
        const float* bo_  = bo   + (size_t)l * EE;
        const float* w1   = pw + OFF_W1 + (size_t)l * FF * EE;
        const float* b1_  = b1   + (size_t)l * FF;
        const float* w2   = pw + OFF_W2 + (size_t)l * EE * FF;
        const float* b2_  = b2   + (size_t)l * EE;

        // pre-LN attention (LN output rounded, standard layout)
        ln_kernel<<<MTOK, 128>>>(px, ln1g + l * EE, ln1b + l * EE, pa);
        // QKV: A pre-rounded raw bits; output rounded (feeds flash)
        run_mm<0, false, true>(pa, wqkv, bqk, pq, MTOK, 3 * EE, EE, EE, EE, 3 * EE);

        // fused flash attention: qkv -> o (rounded standard out)
        {
            dim3 grid(SS / 128, BB * HH);
            flash_kernel<<<grid, 256, FL_SMEM>>>(pq, po);
        }

        // x += O @ Wo^T + bo (A pre-rounded; residual f32 out)
        run_mm<2, false, false>(po, wo, bo_, px, MTOK, EE, EE, EE, EE, EE);

        // pre-LN FFN
        ln_kernel<<<MTOK, 128>>>(px, ln2g + l * EE, ln2b + l * EE, pa);
        // FFN1: A pre-rounded; gelu out rounded (feeds FFN2)
        run_mm<1, false, true>(pa, w1, b1_, pf, MTOK, FF, EE, EE, EE, FF);
        // FFN2: A pre-rounded; residual f32 out
        run_mm<2, false, false>(pf, w2, b2_, px, MTOK, EE, FF, FF, FF, EE);
    }

    // recurrence x-part (A = raw residual f32 -> cvt)
    run_mm<0, true, false>(px, pw + OFF_WI, bi2h, pxp, MTOK, EE, EE, EE, 2 * EE, EE);

    // sequential recurrence (persistent, clustered; original f32 Wi2h)
    recur_kernel<<<128, 256>>>(pxp, h0, Wi2h, ph);

    // head: logits + sigmoid
    head_kernel<<<BB, 512>>>(ph, Wh2o, bh2o, Wc, bc, out, out_size / 2);
}